// round 1
// baseline (speedup 1.0000x reference)
#include <cuda_runtime.h>
#include <cuda_bf16.h>
#include <math.h>

#define NN 50000
#define EE 800000
#define F 128
#define KORD 3
#define BN_EPS 1e-5f

// ---------------- scratch (device globals; allocation-free) ----------------
__device__ float g_xk[NN * 384];      // [n][k][o], 76.8 MB
__device__ float g_proj[NN * 3];      // per-node attW @ feature
__device__ float g_att[EE];           // att, then reused as exp(att - m)
__device__ float g_inv[EE];           // 1/(||dc||^2+1)
__device__ float g_m[NN];             // segment max
__device__ float g_den[NN];           // segment sum of exp
__device__ float g_h[NN * F];         // aggregated messages
__device__ float g_sum[F];            // BN partial sums
__device__ float g_sum2[F];

// ---------------- helpers ----------------
__device__ __forceinline__ void atomicMaxF(float* addr, float v) {
    if (v >= 0.f) {
        atomicMax((int*)addr, __float_as_int(v));
    } else {
        atomicMin((unsigned int*)addr, __float_as_uint(v));
    }
}

// ---------------- kernels ----------------
__global__ void k_init(int n) {
    int i = blockIdx.x * blockDim.x + threadIdx.x;
    if (i < n * F) g_h[i] = 0.f;
    if (i < n) { g_m[i] = -INFINITY; g_den[i] = 0.f; }
    if (i < F) { g_sum[i] = 0.f; g_sum2[i] = 0.f; }
}

// proj[n][e] = dot(attW[e,:], feature[n,:])  — one warp per node
__global__ void k_proj(const float* __restrict__ feat,
                       const float* __restrict__ attW, int n) {
    int w = (blockIdx.x * blockDim.x + threadIdx.x) >> 5;
    int lane = threadIdx.x & 31;
    if (w >= n) return;
    float4 f = reinterpret_cast<const float4*>(feat + (size_t)w * F)[lane];
    const float4* aw = reinterpret_cast<const float4*>(attW);
    float4 w0 = aw[lane];
    float4 w1 = aw[32 + lane];
    float4 w2 = aw[64 + lane];
    float a0 = f.x * w0.x + f.y * w0.y + f.z * w0.z + f.w * w0.w;
    float a1 = f.x * w1.x + f.y * w1.y + f.z * w1.z + f.w * w1.w;
    float a2 = f.x * w2.x + f.y * w2.y + f.z * w2.z + f.w * w2.w;
#pragma unroll
    for (int off = 16; off; off >>= 1) {
        a0 += __shfl_down_sync(0xffffffffu, a0, off);
        a1 += __shfl_down_sync(0xffffffffu, a1, off);
        a2 += __shfl_down_sync(0xffffffffu, a2, off);
    }
    if (lane == 0) {
        g_proj[w * 3 + 0] = a0;
        g_proj[w * 3 + 1] = a1;
        g_proj[w * 3 + 2] = a2;
    }
}

// xk[n][k][o] = sum_i feature[n][i] * linear[k][i][o]
// 16 rows per block, 128 threads (thread = output column o)
__global__ void k_xk(const float* __restrict__ feat,
                     const float* __restrict__ lin, int n) {
    __shared__ float sf[16][F];
    int row0 = blockIdx.x * 16;
    int t = threadIdx.x;
#pragma unroll
    for (int r = 0; r < 16; r++)
        sf[r][t] = feat[(size_t)(row0 + r) * F + t];
    __syncthreads();
    float a0[16], a1[16], a2[16];
#pragma unroll
    for (int r = 0; r < 16; r++) { a0[r] = 0.f; a1[r] = 0.f; a2[r] = 0.f; }
#pragma unroll 4
    for (int i = 0; i < F; i++) {
        float w0 = lin[0 * F * F + i * F + t];
        float w1 = lin[1 * F * F + i * F + t];
        float w2 = lin[2 * F * F + i * F + t];
#pragma unroll
        for (int r = 0; r < 16; r++) {
            float f = sf[r][i];
            a0[r] += f * w0;
            a1[r] += f * w1;
            a2[r] += f * w2;
        }
    }
#pragma unroll
    for (int r = 0; r < 16; r++) {
        size_t base = (size_t)(row0 + r) * 384;
        g_xk[base + t] = a0[r];
        g_xk[base + 128 + t] = a1[r];
        g_xk[base + 256 + t] = a2[r];
    }
}

// edge pass A: att, invdist, segment max
__global__ void k_edgeA(const int* __restrict__ src, const int* __restrict__ dst,
                        const float* __restrict__ coords, int e) {
    int i = blockIdx.x * blockDim.x + threadIdx.x;
    if (i >= e) return;
    int s = src[i], d = dst[i];
    float dx = coords[s * 3 + 0] - coords[d * 3 + 0];
    float dy = coords[s * 3 + 1] - coords[d * 3 + 1];
    float dz = coords[s * 3 + 2] - coords[d * 3 + 2];
    float a = dx * g_proj[s * 3 + 0] + dy * g_proj[s * 3 + 1] + dz * g_proj[s * 3 + 2];
    g_att[i] = a;
    g_inv[i] = 1.f / (dx * dx + dy * dy + dz * dz + 1.f);
    atomicMaxF(&g_m[d], a);
}

// edge pass B: ex = exp(att - m[dst]); denom += ex
__global__ void k_edgeB(const int* __restrict__ dst, int e) {
    int i = blockIdx.x * blockDim.x + threadIdx.x;
    if (i >= e) return;
    int d = dst[i];
    float ex = expf(g_att[i] - g_m[d]);
    g_att[i] = ex;
    atomicAdd(&g_den[d], ex);
}

// edge pass C: h[dst] += (ex/den * invdist) * xk[order, src]   (warp per edge)
__global__ void k_edgeC(const int* __restrict__ src, const int* __restrict__ dst,
                        const int* __restrict__ order, int e) {
    int w = (blockIdx.x * blockDim.x + threadIdx.x) >> 5;
    int lane = threadIdx.x & 31;
    if (w >= e) return;
    int s = src[w], d = dst[w], k = order[w];
    float dn = g_den[d];
    float wt = g_att[w] * g_inv[w] / (dn > 0.f ? dn : 1.f);
    const float4* mp = reinterpret_cast<const float4*>(g_xk + (size_t)(s * 3 + k) * F);
    float4 v = mp[lane];
    float* hp = g_h + (size_t)d * F + lane * 4;
    atomicAdd(hp + 0, v.x * wt);
    atomicAdd(hp + 1, v.y * wt);
    atomicAdd(hp + 2, v.z * wt);
    atomicAdd(hp + 3, v.w * wt);
}

// MLP: y = relu(h @ mlp_w^T + b), write y to out, accumulate BN sums
// 16 rows per block, 128 threads (thread = output column o)
__global__ void k_mlp(const float* __restrict__ mlp_w,
                      const float* __restrict__ mlp_b,
                      float* __restrict__ out, int n) {
    extern __shared__ float smem[];
    float* swT = smem;               // [128][129] : swT[i*129+o] = mlp_w[o*128+i]
    float* sh = smem + 128 * 129;    // [16][128]
    int t = threadIdx.x;
    int row0 = blockIdx.x * 16;
#pragma unroll 4
    for (int j = 0; j < F; j++)      // thread t reads mlp_w[j][t] -> swT[t][j]
        swT[t * 129 + j] = mlp_w[j * F + t];
#pragma unroll
    for (int r = 0; r < 16; r++)
        sh[r * F + t] = g_h[(size_t)(row0 + r) * F + t];
    __syncthreads();

    float acc[16];
#pragma unroll
    for (int r = 0; r < 16; r++) acc[r] = 0.f;
#pragma unroll 4
    for (int i = 0; i < F; i++) {
        float wv = swT[i * 129 + t];
#pragma unroll
        for (int r = 0; r < 16; r++) acc[r] += sh[r * F + i] * wv;
    }
    float b = mlp_b[t];
    float s1 = 0.f, s2 = 0.f;
#pragma unroll
    for (int r = 0; r < 16; r++) {
        float y = acc[r] + b;
        y = y > 0.f ? y : 0.f;
        out[(size_t)(row0 + r) * F + t] = y;
        s1 += y;
        s2 += y * y;
    }
    atomicAdd(&g_sum[t], s1);
    atomicAdd(&g_sum2[t], s2);
}

// BN normalize (training-mode batch stats, biased var)
__global__ void k_bn(float* __restrict__ out, const float* __restrict__ gamma,
                     const float* __restrict__ beta, int n) {
    int i = blockIdx.x * blockDim.x + threadIdx.x;
    if (i >= n * F) return;
    int o = i & (F - 1);
    float inv_n = 1.f / (float)n;
    float mean = g_sum[o] * inv_n;
    float var = g_sum2[o] * inv_n - mean * mean;
    float y = out[i];
    out[i] = (y - mean) * rsqrtf(var + BN_EPS) * gamma[o] + beta[o];
}

// ---------------- launch ----------------
extern "C" void kernel_launch(void* const* d_in, const int* in_sizes, int n_in,
                              void* d_out, int out_size) {
    const float* feature = (const float*)d_in[0];
    const float* coords = (const float*)d_in[1];
    const int* src = (const int*)d_in[2];
    const int* dst = (const int*)d_in[3];
    const int* order = (const int*)d_in[4];
    const float* linear = (const float*)d_in[5];
    const float* attW = (const float*)d_in[6];
    const float* mlp_w = (const float*)d_in[7];
    const float* mlp_b = (const float*)d_in[8];
    const float* bn_gamma = (const float*)d_in[9];
    const float* bn_beta = (const float*)d_in[10];
    float* out = (float*)d_out;

    int n = in_sizes[0] / F;   // 50000
    int e = in_sizes[2];       // 800000

    k_init<<<(n * F + 255) / 256, 256>>>(n);
    k_proj<<<(n * 32 + 255) / 256, 256>>>(feature, attW, n);
    k_xk<<<(n + 15) / 16, 128>>>(feature, linear, n);
    k_edgeA<<<(e + 255) / 256, 256>>>(src, dst, coords, e);
    k_edgeB<<<(e + 255) / 256, 256>>>(dst, e);
    k_edgeC<<<(e * 32 + 255) / 256, 256>>>(src, dst, order, e);

    int smem = (128 * 129 + 16 * F) * (int)sizeof(float);
    cudaFuncSetAttribute(k_mlp, cudaFuncAttributeMaxDynamicSharedMemorySize, smem);
    k_mlp<<<(n + 15) / 16, 128, smem>>>(mlp_w, mlp_b, out, n);
    k_bn<<<(n * F + 255) / 256, 256>>>(out, bn_gamma, bn_beta, n);
}

// round 2
// speedup vs baseline: 1.4063x; 1.4063x over previous
#include <cuda_runtime.h>
#include <cuda_bf16.h>
#include <math.h>

#define NN 50000
#define EE 800000
#define F 128
#define BN_EPS 1e-5f
#define SCAN_B 1024
#define NBLK ((NN + SCAN_B - 1) / SCAN_B)   // 49

// ---------------- scratch (device globals; allocation-free) ----------------
__device__ float g_xk[NN * 384];          // [n][k][o]
__device__ float g_proj[NN * 3];
__device__ float g_att[EE];               // att, then ex
__device__ float g_inv[EE];
__device__ float g_m[NN];
__device__ float g_den[NN];
__device__ float g_h[NN * F];
__device__ float g_sum[F];
__device__ float g_sum2[F];
__device__ int   g_cnt[NN];               // per-dst degree
__device__ int   g_scan[NN];              // block-inclusive scan
__device__ int   g_bsum[NBLK];
__device__ int   g_boff[NBLK];
__device__ int   g_off[NN + 1];           // CSR offsets
__device__ int   g_cur[NN];               // scatter cursors
__device__ long long g_pack[EE];          // {w=ex*inv (hi), xk_row (lo)} in CSR order

__device__ __forceinline__ void atomicMaxF(float* addr, float v) {
    if (v >= 0.f) atomicMax((int*)addr, __float_as_int(v));
    else          atomicMin((unsigned int*)addr, __float_as_uint(v));
}

// ---------------- kernels ----------------
__global__ void k_init(int n) {
    int i = blockIdx.x * blockDim.x + threadIdx.x;
    if (i < n) { g_m[i] = -INFINITY; g_den[i] = 0.f; g_cnt[i] = 0; }
    if (i < F) { g_sum[i] = 0.f; g_sum2[i] = 0.f; }
}

// per-node 3-vector projection: proj[n][e] = dot(attW[:,e]... = attW^T f
__global__ void k_proj(const float* __restrict__ feat,
                       const float* __restrict__ attW, int n) {
    int w = (blockIdx.x * blockDim.x + threadIdx.x) >> 5;
    int lane = threadIdx.x & 31;
    if (w >= n) return;
    float4 f = reinterpret_cast<const float4*>(feat + (size_t)w * F)[lane];
    const float4* aw = reinterpret_cast<const float4*>(attW);
    float4 w0 = aw[lane], w1 = aw[32 + lane], w2 = aw[64 + lane];
    float a0 = f.x * w0.x + f.y * w0.y + f.z * w0.z + f.w * w0.w;
    float a1 = f.x * w1.x + f.y * w1.y + f.z * w1.z + f.w * w1.w;
    float a2 = f.x * w2.x + f.y * w2.y + f.z * w2.z + f.w * w2.w;
#pragma unroll
    for (int off = 16; off; off >>= 1) {
        a0 += __shfl_down_sync(0xffffffffu, a0, off);
        a1 += __shfl_down_sync(0xffffffffu, a1, off);
        a2 += __shfl_down_sync(0xffffffffu, a2, off);
    }
    if (lane == 0) {
        g_proj[w * 3 + 0] = a0; g_proj[w * 3 + 1] = a1; g_proj[w * 3 + 2] = a2;
    }
}

// xk[n][k][o] = sum_i feature[n][i] * linear[k][i][o]
__global__ void k_xk(const float* __restrict__ feat,
                     const float* __restrict__ lin, int n) {
    __shared__ float sf[16][F];
    int row0 = blockIdx.x * 16;
    int t = threadIdx.x;
#pragma unroll
    for (int r = 0; r < 16; r++)
        sf[r][t] = feat[(size_t)(row0 + r) * F + t];
    __syncthreads();
    float a0[16], a1[16], a2[16];
#pragma unroll
    for (int r = 0; r < 16; r++) { a0[r] = 0.f; a1[r] = 0.f; a2[r] = 0.f; }
#pragma unroll 4
    for (int i = 0; i < F; i++) {
        float w0 = lin[0 * F * F + i * F + t];
        float w1 = lin[1 * F * F + i * F + t];
        float w2 = lin[2 * F * F + i * F + t];
#pragma unroll
        for (int r = 0; r < 16; r++) {
            float f = sf[r][i];
            a0[r] += f * w0; a1[r] += f * w1; a2[r] += f * w2;
        }
    }
#pragma unroll
    for (int r = 0; r < 16; r++) {
        size_t base = (size_t)(row0 + r) * 384;
        g_xk[base + t] = a0[r];
        g_xk[base + 128 + t] = a1[r];
        g_xk[base + 256 + t] = a2[r];
    }
}

// edge pass A: att, invdist, segment max, dst histogram
__global__ void k_edgeA(const int* __restrict__ src, const int* __restrict__ dst,
                        const float* __restrict__ coords, int e) {
    int i = blockIdx.x * blockDim.x + threadIdx.x;
    if (i >= e) return;
    int s = src[i], d = dst[i];
    float dx = coords[s * 3 + 0] - coords[d * 3 + 0];
    float dy = coords[s * 3 + 1] - coords[d * 3 + 1];
    float dz = coords[s * 3 + 2] - coords[d * 3 + 2];
    float a = dx * g_proj[s * 3 + 0] + dy * g_proj[s * 3 + 1] + dz * g_proj[s * 3 + 2];
    g_att[i] = a;
    g_inv[i] = 1.f / (dx * dx + dy * dy + dz * dz + 1.f);
    atomicMaxF(&g_m[d], a);
    atomicAdd(&g_cnt[d], 1);
}

// exclusive scan of g_cnt -> g_off / g_cur  (3 small kernels)
__global__ void k_scan_block(int n) {
    __shared__ int s[SCAN_B];
    int g = blockIdx.x * SCAN_B + threadIdx.x;
    int v = (g < n) ? g_cnt[g] : 0;
    s[threadIdx.x] = v;
    __syncthreads();
#pragma unroll
    for (int off = 1; off < SCAN_B; off <<= 1) {
        int t = (threadIdx.x >= off) ? s[threadIdx.x - off] : 0;
        __syncthreads();
        s[threadIdx.x] += t;
        __syncthreads();
    }
    if (g < n) g_scan[g] = s[threadIdx.x];
    if (threadIdx.x == SCAN_B - 1) g_bsum[blockIdx.x] = s[SCAN_B - 1];
}
__global__ void k_scan_top(int nb) {
    if (threadIdx.x == 0) {
        int acc = 0;
        for (int i = 0; i < nb; i++) { g_boff[i] = acc; acc += g_bsum[i]; }
    }
}
__global__ void k_scan_add(int n, int e) {
    int g = blockIdx.x * SCAN_B + threadIdx.x;
    if (g < n) {
        int excl = g_scan[g] - g_cnt[g] + g_boff[blockIdx.x];
        g_off[g] = excl;
        g_cur[g] = excl;
    }
    if (g == 0) g_off[n] = e;
}

// edge pass B: ex, denom; scatter packed record into CSR slot
__global__ void k_edgeB(const int* __restrict__ src, const int* __restrict__ dst,
                        const int* __restrict__ order, int e) {
    int i = blockIdx.x * blockDim.x + threadIdx.x;
    if (i >= e) return;
    int d = dst[i];
    float ex = expf(g_att[i] - g_m[d]);
    atomicAdd(&g_den[d], ex);
    float w = ex * g_inv[i];
    int row = src[i] * 3 + order[i];
    int pos = atomicAdd(&g_cur[d], 1);
    g_pack[pos] = ((long long)__float_as_int(w) << 32) | (unsigned int)row;
}

// aggregation: one warp per dst node, register accumulation, no atomics
__global__ void k_agg(int n) {
    int node = (blockIdx.x * blockDim.x + threadIdx.x) >> 5;
    int lane = threadIdx.x & 31;
    if (node >= n) return;
    int beg = g_off[node], end = g_off[node + 1];
    float den = g_den[node];
    float invden = 1.f / (den > 0.f ? den : 1.f);
    float4 acc = make_float4(0.f, 0.f, 0.f, 0.f);
    for (int base = beg; base < end; base += 32) {
        int idx = base + lane;
        long long pk = (idx < end) ? g_pack[idx] : 0;
        int cnt = min(32, end - base);
        for (int j = 0; j < cnt; j++) {
            long long p = __shfl_sync(0xffffffffu, pk, j);
            int row = (int)(unsigned int)p;
            float w = __int_as_float((int)(p >> 32)) * invden;
            float4 v = reinterpret_cast<const float4*>(g_xk + (size_t)row * F)[lane];
            acc.x += w * v.x; acc.y += w * v.y;
            acc.z += w * v.z; acc.w += w * v.w;
        }
    }
    reinterpret_cast<float4*>(g_h + (size_t)node * F)[lane] = acc;
}

// MLP: y = relu(h @ mlp_w^T + b), accumulate BN sums
__global__ void k_mlp(const float* __restrict__ mlp_w,
                      const float* __restrict__ mlp_b,
                      float* __restrict__ out, int n) {
    extern __shared__ float smem[];
    float* swT = smem;               // [128][129]
    float* sh = smem + 128 * 129;    // [16][128]
    int t = threadIdx.x;
    int row0 = blockIdx.x * 16;
#pragma unroll 4
    for (int j = 0; j < F; j++)
        swT[t * 129 + j] = mlp_w[j * F + t];
#pragma unroll
    for (int r = 0; r < 16; r++)
        sh[r * F + t] = g_h[(size_t)(row0 + r) * F + t];
    __syncthreads();
    float acc[16];
#pragma unroll
    for (int r = 0; r < 16; r++) acc[r] = 0.f;
#pragma unroll 4
    for (int i = 0; i < F; i++) {
        float wv = swT[i * 129 + t];
#pragma unroll
        for (int r = 0; r < 16; r++) acc[r] += sh[r * F + i] * wv;
    }
    float b = mlp_b[t];
    float s1 = 0.f, s2 = 0.f;
#pragma unroll
    for (int r = 0; r < 16; r++) {
        float y = acc[r] + b;
        y = y > 0.f ? y : 0.f;
        out[(size_t)(row0 + r) * F + t] = y;
        s1 += y; s2 += y * y;
    }
    atomicAdd(&g_sum[t], s1);
    atomicAdd(&g_sum2[t], s2);
}

__global__ void k_bn(float* __restrict__ out, const float* __restrict__ gamma,
                     const float* __restrict__ beta, int n) {
    int i = blockIdx.x * blockDim.x + threadIdx.x;
    if (i >= n * F) return;
    int o = i & (F - 1);
    float inv_n = 1.f / (float)n;
    float mean = g_sum[o] * inv_n;
    float var = g_sum2[o] * inv_n - mean * mean;
    float y = out[i];
    out[i] = (y - mean) * rsqrtf(var + BN_EPS) * gamma[o] + beta[o];
}

// ---------------- launch ----------------
extern "C" void kernel_launch(void* const* d_in, const int* in_sizes, int n_in,
                              void* d_out, int out_size) {
    const float* feature = (const float*)d_in[0];
    const float* coords  = (const float*)d_in[1];
    const int*   src     = (const int*)d_in[2];
    const int*   dst     = (const int*)d_in[3];
    const int*   order   = (const int*)d_in[4];
    const float* linear  = (const float*)d_in[5];
    const float* attW    = (const float*)d_in[6];
    const float* mlp_w   = (const float*)d_in[7];
    const float* mlp_b   = (const float*)d_in[8];
    const float* bn_gamma = (const float*)d_in[9];
    const float* bn_beta  = (const float*)d_in[10];
    float* out = (float*)d_out;

    int n = in_sizes[0] / F;   // 50000
    int e = in_sizes[2];       // 800000
    int nb = (n + SCAN_B - 1) / SCAN_B;

    k_init<<<(n + 255) / 256, 256>>>(n);
    k_proj<<<(n * 32 + 255) / 256, 256>>>(feature, attW, n);
    k_xk<<<(n + 15) / 16, 128>>>(feature, linear, n);
    k_edgeA<<<(e + 255) / 256, 256>>>(src, dst, coords, e);
    k_scan_block<<<nb, SCAN_B>>>(n);
    k_scan_top<<<1, 32>>>(nb);
    k_scan_add<<<nb, SCAN_B>>>(n, e);
    k_edgeB<<<(e + 255) / 256, 256>>>(src, dst, order, e);
    k_agg<<<(n * 32 + 255) / 256, 256>>>(n);

    int smem = (128 * 129 + 16 * F) * (int)sizeof(float);
    cudaFuncSetAttribute(k_mlp, cudaFuncAttributeMaxDynamicSharedMemorySize, smem);
    k_mlp<<<(n + 15) / 16, 128, smem>>>(mlp_w, mlp_b, out, n);
    k_bn<<<(n * F + 255) / 256, 256>>>(out, bn_gamma, bn_beta, n);
}

// round 3
// speedup vs baseline: 1.8403x; 1.3086x over previous
#include <cuda_runtime.h>
#include <cuda_bf16.h>
#include <math.h>

#define NN 50000
#define EE 800000
#define F 128
#define BN_EPS 1e-5f
#define SCAN_B 1024
#define NBLK ((NN + SCAN_B - 1) / SCAN_B)

// ---------------- scratch ----------------
__device__ float g_agg[NN * 384];         // [n][k*128+o] aggregated features
__device__ float g_M[384 * 128];          // L @ W^T folded matrix
__device__ float g_proj[NN * 3];
__device__ float g_att[EE];
__device__ float g_inv[EE];
__device__ float g_m[NN];
__device__ float g_den[NN];
__device__ float g_sum[F];
__device__ float g_sum2[F];
__device__ int   g_cnt[NN];
__device__ int   g_scan[NN];
__device__ int   g_bsum[NBLK];
__device__ int   g_boff[NBLK];
__device__ int   g_off[NN + 1];
__device__ int   g_cur[NN];
__device__ long long g_pack[EE];          // {w (hi 32), src*4+order (lo 32)}

__device__ __forceinline__ void atomicMaxF(float* addr, float v) {
    if (v >= 0.f) atomicMax((int*)addr, __float_as_int(v));
    else          atomicMin((unsigned int*)addr, __float_as_uint(v));
}

// ---------------- kernels ----------------
__global__ void k_init(int n) {
    int i = blockIdx.x * blockDim.x + threadIdx.x;
    if (i < n) { g_m[i] = -INFINITY; g_den[i] = 0.f; g_cnt[i] = 0; }
    if (i < F) { g_sum[i] = 0.f; g_sum2[i] = 0.f; }
}

__global__ void k_proj(const float* __restrict__ feat,
                       const float* __restrict__ attW, int n) {
    int w = (blockIdx.x * blockDim.x + threadIdx.x) >> 5;
    int lane = threadIdx.x & 31;
    if (w >= n) return;
    float4 f = reinterpret_cast<const float4*>(feat + (size_t)w * F)[lane];
    const float4* aw = reinterpret_cast<const float4*>(attW);
    float4 w0 = aw[lane], w1 = aw[32 + lane], w2 = aw[64 + lane];
    float a0 = f.x * w0.x + f.y * w0.y + f.z * w0.z + f.w * w0.w;
    float a1 = f.x * w1.x + f.y * w1.y + f.z * w1.z + f.w * w1.w;
    float a2 = f.x * w2.x + f.y * w2.y + f.z * w2.z + f.w * w2.w;
#pragma unroll
    for (int off = 16; off; off >>= 1) {
        a0 += __shfl_down_sync(0xffffffffu, a0, off);
        a1 += __shfl_down_sync(0xffffffffu, a1, off);
        a2 += __shfl_down_sync(0xffffffffu, a2, off);
    }
    if (lane == 0) {
        g_proj[w * 3 + 0] = a0; g_proj[w * 3 + 1] = a1; g_proj[w * 3 + 2] = a2;
    }
}

// edge pass A: att, invdist, segment max, dst histogram
__global__ void k_edgeA(const int* __restrict__ src, const int* __restrict__ dst,
                        const float* __restrict__ coords, int e) {
    int i = blockIdx.x * blockDim.x + threadIdx.x;
    if (i >= e) return;
    int s = src[i], d = dst[i];
    float dx = coords[s * 3 + 0] - coords[d * 3 + 0];
    float dy = coords[s * 3 + 1] - coords[d * 3 + 1];
    float dz = coords[s * 3 + 2] - coords[d * 3 + 2];
    float a = dx * g_proj[s * 3 + 0] + dy * g_proj[s * 3 + 1] + dz * g_proj[s * 3 + 2];
    g_att[i] = a;
    g_inv[i] = 1.f / (dx * dx + dy * dy + dz * dz + 1.f);
    atomicMaxF(&g_m[d], a);
    atomicAdd(&g_cnt[d], 1);
}

__global__ void k_scan_block(int n) {
    __shared__ int s[SCAN_B];
    int g = blockIdx.x * SCAN_B + threadIdx.x;
    int v = (g < n) ? g_cnt[g] : 0;
    s[threadIdx.x] = v;
    __syncthreads();
#pragma unroll
    for (int off = 1; off < SCAN_B; off <<= 1) {
        int t = (threadIdx.x >= off) ? s[threadIdx.x - off] : 0;
        __syncthreads();
        s[threadIdx.x] += t;
        __syncthreads();
    }
    if (g < n) g_scan[g] = s[threadIdx.x];
    if (threadIdx.x == SCAN_B - 1) g_bsum[blockIdx.x] = s[SCAN_B - 1];
}
__global__ void k_scan_top(int nb) {
    if (threadIdx.x == 0) {
        int acc = 0;
        for (int i = 0; i < nb; i++) { g_boff[i] = acc; acc += g_bsum[i]; }
    }
}
__global__ void k_scan_add(int n, int e) {
    int g = blockIdx.x * SCAN_B + threadIdx.x;
    if (g < n) {
        int excl = g_scan[g] - g_cnt[g] + g_boff[blockIdx.x];
        g_off[g] = excl;
        g_cur[g] = excl;
    }
    if (g == 0) g_off[n] = e;
}

// edge pass B: ex, denom; pack {w, src*4+order} into CSR slot
__global__ void k_edgeB(const int* __restrict__ src, const int* __restrict__ dst,
                        const int* __restrict__ order, int e) {
    int i = blockIdx.x * blockDim.x + threadIdx.x;
    if (i >= e) return;
    int d = dst[i];
    float ex = expf(g_att[i] - g_m[d]);
    atomicAdd(&g_den[d], ex);
    float w = ex * g_inv[i];
    int idx = src[i] * 4 + order[i];
    int pos = atomicAdd(&g_cur[d], 1);
    g_pack[pos] = ((long long)__float_as_int(w) << 32) | (unsigned int)idx;
}

// aggregation: warp per dst node; gather raw features, 3 order-accumulators
__global__ void k_agg(const float* __restrict__ feat, int n) {
    int node = (blockIdx.x * blockDim.x + threadIdx.x) >> 5;
    int lane = threadIdx.x & 31;
    if (node >= n) return;
    int beg = g_off[node], end = g_off[node + 1];
    float den = g_den[node];
    float invden = 1.f / (den > 0.f ? den : 1.f);
    float4 a0 = make_float4(0.f, 0.f, 0.f, 0.f);
    float4 a1 = a0, a2 = a0;
    const float4* f4 = reinterpret_cast<const float4*>(feat);
    for (int base = beg; base < end; base += 32) {
        int idx = base + lane;
        long long pk = (idx < end) ? g_pack[idx] : 0;
        int cnt = min(32, end - base);
        for (int j = 0; j < cnt; j++) {
            long long p = __shfl_sync(0xffffffffu, pk, j);
            int id = (int)(unsigned int)p;
            int s = id >> 2, k = id & 3;
            float w = __int_as_float((int)(p >> 32)) * invden;
            float4 v = f4[(size_t)s * 32 + lane];
            if (k == 0) {
                a0.x += w * v.x; a0.y += w * v.y; a0.z += w * v.z; a0.w += w * v.w;
            } else if (k == 1) {
                a1.x += w * v.x; a1.y += w * v.y; a1.z += w * v.z; a1.w += w * v.w;
            } else {
                a2.x += w * v.x; a2.y += w * v.y; a2.z += w * v.z; a2.w += w * v.w;
            }
        }
    }
    float4* ap = reinterpret_cast<float4*>(g_agg + (size_t)node * 384);
    ap[lane] = a0;
    ap[32 + lane] = a1;
    ap[64 + lane] = a2;
}

// fold: M[r][o] = sum_j linear[r/128][r%128][j] * mlp_w[o][j]   (16 rows/block)
__global__ void k_prep(const float* __restrict__ lin, const float* __restrict__ W) {
    extern __shared__ float smem[];
    float* swT = smem;              // [128][129]: swT[t][j] ... stores W^T pieces
    float* sL = smem + 128 * 129;   // [16][128]
    int t = threadIdx.x;
    int r0 = blockIdx.x * 16;
#pragma unroll 4
    for (int j = 0; j < F; j++)     // swT[j][t'] layout: swT[t*129+j] = W[j][t]
        swT[t * 129 + j] = W[j * F + t];
    for (int idx = t; idx < 16 * F; idx += F)
        sL[idx] = lin[(size_t)r0 * F + idx];
    __syncthreads();
    float acc[16];
#pragma unroll
    for (int r = 0; r < 16; r++) acc[r] = 0.f;
    // M[r][t] = sum_j L[r][j] * W[t][j];  W[t][j] = swT[j? -> stored swT[t'][j'] = W[j'][t']
    // we need W[t][j]: that's swT[j * 129 + t]
#pragma unroll 4
    for (int j = 0; j < F; j++) {
        float wv = swT[j * 129 + t];
#pragma unroll
        for (int r = 0; r < 16; r++) acc[r] += sL[r * F + j] * wv;
    }
#pragma unroll
    for (int r = 0; r < 16; r++)
        g_M[(size_t)(r0 + r) * F + t] = acc[r];
}

// fused output GEMM: out = relu(Agg[N,384] @ M[384,128] + b), BN sums
// tile 128x128, BK=8, 256 threads, 8x8 per thread (split 2x2 of 4x4)
__global__ void k_out(const float* __restrict__ mlp_b,
                      float* __restrict__ out, int n) {
    __shared__ float As[8][132];
    __shared__ float Bs[8][128];
    __shared__ float ssum[128], ssum2[128];
    int tid = threadIdx.x;
    int tx = tid & 15, ty = tid >> 4;
    int row0 = blockIdx.x * 128;

    if (tid < 128) { ssum[tid] = 0.f; ssum2[tid] = 0.f; }

    float acc[8][8];
#pragma unroll
    for (int i = 0; i < 8; i++)
#pragma unroll
        for (int j = 0; j < 8; j++) acc[i][j] = 0.f;

    int arow = row0 + (tid >> 1);
    int akq = (tid & 1) * 4;
    int brow = tid >> 5;
    int bcol = (tid & 31) * 4;

    for (int k0 = 0; k0 < 384; k0 += 8) {
        float4 av = make_float4(0.f, 0.f, 0.f, 0.f);
        if (arow < n)
            av = *reinterpret_cast<const float4*>(g_agg + (size_t)arow * 384 + k0 + akq);
        float4 bv = *reinterpret_cast<const float4*>(g_M + (size_t)(k0 + brow) * F + bcol);
        __syncthreads();
        int m = tid >> 1;
        As[akq + 0][m] = av.x; As[akq + 1][m] = av.y;
        As[akq + 2][m] = av.z; As[akq + 3][m] = av.w;
        *reinterpret_cast<float4*>(&Bs[brow][bcol]) = bv;
        __syncthreads();
#pragma unroll
        for (int kk = 0; kk < 8; kk++) {
            float4 a0 = *reinterpret_cast<float4*>(&As[kk][ty * 4]);
            float4 a1 = *reinterpret_cast<float4*>(&As[kk][64 + ty * 4]);
            float4 b0 = *reinterpret_cast<float4*>(&Bs[kk][tx * 4]);
            float4 b1 = *reinterpret_cast<float4*>(&Bs[kk][64 + tx * 4]);
            float ar[8] = {a0.x, a0.y, a0.z, a0.w, a1.x, a1.y, a1.z, a1.w};
            float br[8] = {b0.x, b0.y, b0.z, b0.w, b1.x, b1.y, b1.z, b1.w};
#pragma unroll
            for (int i = 0; i < 8; i++)
#pragma unroll
                for (int j = 0; j < 8; j++) acc[i][j] += ar[i] * br[j];
        }
    }

    // epilogue: bias, relu, store, BN partial sums
    float bias[8];
#pragma unroll
    for (int j = 0; j < 8; j++) {
        int col = (j < 4) ? tx * 4 + j : 64 + tx * 4 + (j - 4);
        bias[j] = mlp_b[col];
    }
    float s1[8], s2[8];
#pragma unroll
    for (int j = 0; j < 8; j++) { s1[j] = 0.f; s2[j] = 0.f; }
#pragma unroll
    for (int i = 0; i < 8; i++) {
        int row = row0 + ((i < 4) ? ty * 4 + i : 64 + ty * 4 + (i - 4));
        if (row >= n) continue;
#pragma unroll
        for (int j = 0; j < 8; j++) {
            int col = (j < 4) ? tx * 4 + j : 64 + tx * 4 + (j - 4);
            float y = acc[i][j] + bias[j];
            y = y > 0.f ? y : 0.f;
            out[(size_t)row * F + col] = y;
            s1[j] += y; s2[j] += y * y;
        }
    }
#pragma unroll
    for (int j = 0; j < 8; j++) {
        int col = (j < 4) ? tx * 4 + j : 64 + tx * 4 + (j - 4);
        atomicAdd(&ssum[col], s1[j]);
        atomicAdd(&ssum2[col], s2[j]);
    }
    __syncthreads();
    if (tid < 128) {
        atomicAdd(&g_sum[tid], ssum[tid]);
        atomicAdd(&g_sum2[tid], ssum2[tid]);
    }
}

__global__ void k_bn(float* __restrict__ out, const float* __restrict__ gamma,
                     const float* __restrict__ beta, int n) {
    int i = blockIdx.x * blockDim.x + threadIdx.x;
    if (i >= n * F) return;
    int o = i & (F - 1);
    float inv_n = 1.f / (float)n;
    float mean = g_sum[o] * inv_n;
    float var = g_sum2[o] * inv_n - mean * mean;
    float y = out[i];
    out[i] = (y - mean) * rsqrtf(var + BN_EPS) * gamma[o] + beta[o];
}

// ---------------- launch ----------------
extern "C" void kernel_launch(void* const* d_in, const int* in_sizes, int n_in,
                              void* d_out, int out_size) {
    const float* feature = (const float*)d_in[0];
    const float* coords  = (const float*)d_in[1];
    const int*   src     = (const int*)d_in[2];
    const int*   dst     = (const int*)d_in[3];
    const int*   order   = (const int*)d_in[4];
    const float* linear  = (const float*)d_in[5];
    const float* attW    = (const float*)d_in[6];
    const float* mlp_w   = (const float*)d_in[7];
    const float* mlp_b   = (const float*)d_in[8];
    const float* bn_gamma = (const float*)d_in[9];
    const float* bn_beta  = (const float*)d_in[10];
    float* out = (float*)d_out;

    int n = in_sizes[0] / F;   // 50000
    int e = in_sizes[2];       // 800000
    int nb = (n + SCAN_B - 1) / SCAN_B;

    k_init<<<(n + 255) / 256, 256>>>(n);
    k_proj<<<(n * 32 + 255) / 256, 256>>>(feature, attW, n);

    int smemp = (128 * 129 + 16 * F) * (int)sizeof(float);
    cudaFuncSetAttribute(k_prep, cudaFuncAttributeMaxDynamicSharedMemorySize, smemp);
    k_prep<<<384 / 16, 128, smemp>>>(linear, mlp_w);

    k_edgeA<<<(e + 255) / 256, 256>>>(src, dst, coords, e);
    k_scan_block<<<nb, SCAN_B>>>(n);
    k_scan_top<<<1, 32>>>(nb);
    k_scan_add<<<nb, SCAN_B>>>(n, e);
    k_edgeB<<<(e + 255) / 256, 256>>>(src, dst, order, e);
    k_agg<<<(n * 32 + 255) / 256, 256>>>(feature, n);

    k_out<<<(n + 127) / 128, 256>>>(mlp_b, out, n);
    k_bn<<<(n * F + 255) / 256, 256>>>(out, bn_gamma, bn_beta, n);
}